// round 16
// baseline (speedup 1.0000x reference)
#include <cuda_runtime.h>
#include <cuda_bf16.h>
#include <math.h>
#include <stdint.h>

// Problem constants (fixed by the reference setup)
#define BS   2
#define T_   4
#define HS   32
#define WS   32
#define HW   (HS*WS)          // 1024
#define LQ   (T_*HW)          // 4096
#define M_TOK (BS*LQ)         // 8192 rows
#define D_   256
#define NH   8
#define NL   4
#define NP   4
#define HD   32               // D/NH
#define DFFN 1024
#define X_ELEMS   (BS*LQ*D_)              // 2097152 (output x)

// ---------------- scratch (no allocations allowed) ----------------
__device__ __nv_bfloat16 g_src_h[M_TOK * D_];
// transposed weights [N][K], hi/lo; fused layout: vp | so | aw | op | l1 | l2
#define WOFF_VP 0
#define WOFF_SO 65536
#define WOFF_AW 131072
#define WOFF_OP 163840
#define WOFF_L1 229376
#define WOFF_L2 491520
#define W_TOTAL 753664
__device__ __nv_bfloat16 g_w_h[W_TOTAL];
__device__ __nv_bfloat16 g_w_l[W_TOTAL];

__device__ float g_value[M_TOK * D_];        // value fp32 for gather
__device__ float g_aw[M_TOK * 128];          // attention LOGITS (softmax fused in gather)
__device__ __nv_bfloat16 g_attn_h[M_TOK * D_];
__device__ float g_tmpf[M_TOK * D_];         // pre-LN buffer (reused)
__device__ float g_x1[M_TOK * D_];           // after LN1 (fp32 residual for FFN2)
__device__ __nv_bfloat16 g_x1_h[M_TOK * D_];
__device__ __nv_bfloat16 g_ffn_h[M_TOK * DFFN];

// ---------------- warp MMA helpers (baseline PTX, no 'a' features) --------
__device__ __forceinline__ uint32_t smem_u32(const void* p) {
    uint32_t a;
    asm("{ .reg .u64 t; cvta.to.shared.u64 t, %1; cvt.u32.u64 %0, t; }" : "=r"(a) : "l"(p));
    return a;
}
__device__ __forceinline__ void ldm_x4(uint32_t* r, uint32_t addr) {
    asm volatile("ldmatrix.sync.aligned.m8n8.x4.shared.b16 {%0,%1,%2,%3}, [%4];"
                 : "=r"(r[0]), "=r"(r[1]), "=r"(r[2]), "=r"(r[3]) : "r"(addr));
}
__device__ __forceinline__ void mma_bf16(float* c, const uint32_t* a, const uint32_t* b) {
    asm volatile("mma.sync.aligned.m16n8k16.row.col.f32.bf16.bf16.f32 "
                 "{%0,%1,%2,%3}, {%4,%5,%6,%7}, {%8,%9}, {%0,%1,%2,%3};"
                 : "+f"(c[0]), "+f"(c[1]), "+f"(c[2]), "+f"(c[3])
                 : "r"(a[0]), "r"(a[1]), "r"(a[2]), "r"(a[3]), "r"(b[0]), "r"(b[1]));
}
#define CP16(dst, src) \
    asm volatile("cp.async.cg.shared.global [%0], [%1], 16;" :: "r"(dst), "l"(src))
#define CP_COMMIT() asm volatile("cp.async.commit_group;" ::: "memory")
#define CP_WAIT1()  asm volatile("cp.async.wait_group 1;"  ::: "memory")

// ---------------- 2-pass bf16 GEMM: D = A·Wh + A·Wl (A plain bf16) ---------
// EPI: 2 = relu -> bf16   3 = +bias+res (fp32)
//      4 = fused src-projections: region by n0: [0,256)=value fp32,
//          [256,512)=sampling-loc, [512,640)=attn logits
#define AST 40                    // smem row stride (bf16): 80B rows, 16B aligned
#define SSTR 20480                // bytes per pipeline stage (A 10240 + Bh 5120 + Bl 5120)
#define OFF_BH 10240
#define OFF_BL 15360
#define SMEM_TOT (2 * SSTR)       // 40960 B dynamic smem

template<int EPI>
__global__ __launch_bounds__(256)
void mma_gemm(const __nv_bfloat16* __restrict__ A,
              const __nv_bfloat16* __restrict__ Bhi, const __nv_bfloat16* __restrict__ Blo,
              const float* __restrict__ bias, const float* __restrict__ bias2,
              const float* __restrict__ bias3,
              const float* __restrict__ res, const float* __restrict__ ref,
              float* __restrict__ C, float* __restrict__ C2, float* __restrict__ C3,
              __nv_bfloat16* __restrict__ Chi,
              int N, int K)
{
    extern __shared__ char smem[];
    const uint32_t sb = smem_u32(smem);

    const int tid  = threadIdx.x;
    const int wid  = tid >> 5;
    const int lane = tid & 31;
    const int wm   = wid >> 1;          // 0..3  (M dir, 32 rows each)
    const int wn   = wid & 1;           // 0..1  (N dir, 32 cols each)
    const int m0   = blockIdx.y * 128;
    const int n0   = blockIdx.x * 64;

    const int seg = lane >> 3;
    const int rr  = lane & 7;

    uint32_t aoff[2], boff[2];
#pragma unroll
    for (int i = 0; i < 2; i++) {
        const int row = wm * 32 + i * 16 + (seg & 1) * 8 + rr;
        aoff[i] = (uint32_t)((row * AST + (seg >> 1) * 8) * 2);
    }
#pragma unroll
    for (int j = 0; j < 2; j++) {
        const int nrow = wn * 32 + j * 16 + ((seg >> 1) ? 8 : 0) + rr;
        boff[j] = (uint32_t)((nrow * AST + (seg & 1) * 8) * 2);
    }

    // per-thread load coords
    const int lrowA = tid >> 2;              // 0..63 (x2 halves for A)
    const int lc8   = (tid & 3) * 8;         // 0,8,16,24
    const uint32_t soA  = (uint32_t)((lrowA * AST + lc8) * 2);
    const uint32_t soA2 = (uint32_t)(((lrowA + 64) * AST + lc8) * 2);
    const uint32_t soB  = soA;

    float acc[2][4][4];
#pragma unroll
    for (int i = 0; i < 2; i++)
#pragma unroll
        for (int j = 0; j < 4; j++)
#pragma unroll
            for (int q = 0; q < 4; q++) acc[i][j][q] = 0.f;

    const int nch = K >> 5;     // K/32

    auto load_stage = [&](int kt, int s) {
        const int kc = kt << 5;
        const uint32_t st = sb + s * SSTR;
        size_t gi = (size_t)(m0 + lrowA) * K + kc + lc8;
        CP16(st + soA, A + gi);
        gi = (size_t)(m0 + 64 + lrowA) * K + kc + lc8;
        CP16(st + soA2, A + gi);
        gi = (size_t)(n0 + lrowA) * K + kc + lc8;
        CP16(st + OFF_BH + soB, Bhi + gi);
        CP16(st + OFF_BL + soB, Blo + gi);
    };

    load_stage(0, 0);
    CP_COMMIT();

    for (int kt = 0; kt < nch; kt++) {
        const int s = kt & 1;
        if (kt + 1 < nch) load_stage(kt + 1, s ^ 1);
        CP_COMMIT();
        CP_WAIT1();
        __syncthreads();

        const uint32_t st = sb + s * SSTR;
#pragma unroll
        for (int kk = 0; kk < 2; kk++) {
            const uint32_t kb = kk * 32;   // 16 bf16 = 32 bytes
            uint32_t ah[2][4], bh[2][4], bl[2][4];
#pragma unroll
            for (int i = 0; i < 2; i++) ldm_x4(ah[i], st + aoff[i] + kb);
#pragma unroll
            for (int j = 0; j < 2; j++) {
                ldm_x4(bh[j], st + OFF_BH + boff[j] + kb);
                ldm_x4(bl[j], st + OFF_BL + boff[j] + kb);
            }
#pragma unroll
            for (int i = 0; i < 2; i++) {
#pragma unroll
                for (int jt = 0; jt < 4; jt++) {
                    const int j = jt >> 1;
                    const int po = (jt & 1) * 2;
                    uint32_t bhp[2] = { bh[j][po], bh[j][po + 1] };
                    uint32_t blp[2] = { bl[j][po], bl[j][po + 1] };
                    mma_bf16(acc[i][jt], ah[i], bhp);
                    mma_bf16(acc[i][jt], ah[i], blp);
                }
            }
        }
        __syncthreads();
    }

    // -------- epilogue --------
    const int tg = lane >> 2;        // row-in-8
    const int t4 = lane & 3;         // col pair group

    int region = 0;
    const float* bptr = bias;
    float* optr = C;
    int oldN = N;
    int colbase = n0;
    if (EPI == 4) {
        if (n0 < 256)      { region = 0; bptr = bias;  optr = C;  oldN = 256; colbase = n0; }
        else if (n0 < 512) { region = 1; bptr = bias2; optr = C2; oldN = 256; colbase = n0 - 256; }
        else               { region = 2; bptr = bias3; optr = C3; oldN = 128; colbase = n0 - 512; }
    }

#pragma unroll
    for (int i = 0; i < 2; i++) {
#pragma unroll
        for (int jt = 0; jt < 4; jt++) {
            const int colg = colbase + wn * 32 + jt * 8 + t4 * 2;  // even col, 2 wide
            const float b0 = bptr[colg];
            const float b1 = bptr[colg + 1];
#pragma unroll
            for (int half = 0; half < 2; half++) {
                const int row = m0 + wm * 32 + i * 16 + tg + half * 8;
                float v0 = acc[i][jt][half * 2 + 0] + b0;
                float v1 = acc[i][jt][half * 2 + 1] + b1;
                if (EPI == 4 && region == 1) {
                    const int l = (colg >> 3) & 3;
                    const float r0 = ref[(size_t)row * 8 + l * 2 + 0];
                    const float r1 = ref[(size_t)row * 8 + l * 2 + 1];
                    v0 = v0 * (1.f / 32.f) + r0;
                    v1 = v1 * (1.f / 32.f) + r1;
                } else if (EPI == 3) {
                    const float2 rv = *(const float2*)(res + (size_t)row * N + colg);
                    v0 += rv.x; v1 += rv.y;
                }
                if (EPI == 2) {
                    v0 = fmaxf(v0, 0.f);
                    v1 = fmaxf(v1, 0.f);
                    __nv_bfloat162 hp;
                    hp.x = __float2bfloat16(v0);
                    hp.y = __float2bfloat16(v1);
                    *(__nv_bfloat162*)(Chi + (size_t)row * N + colg) = hp;
                } else {
                    float2 o; o.x = v0; o.y = v1;
                    *(float2*)(optr + (size_t)row * oldN + colg) = o;
                }
            }
        }
    }
}

// ---------------- fp32 -> bf16 elementwise ----------------
__global__ void conv_h_kernel(const float* __restrict__ x,
                              __nv_bfloat16* __restrict__ h, int n)
{
    const int i = blockIdx.x * blockDim.x + threadIdx.x;
    if (i >= n) return;
    h[i] = __float2bfloat16(x[i]);
}

// ---------------- all-weights transpose + split in one launch --------------
__global__ void prep_all_kernel(const float* __restrict__ vp, const float* __restrict__ so,
                                const float* __restrict__ awW, const float* __restrict__ op,
                                const float* __restrict__ l1, const float* __restrict__ l2,
                                __nv_bfloat16* __restrict__ h, __nv_bfloat16* __restrict__ l)
{
    const int i = blockIdx.x * blockDim.x + threadIdx.x;
    if (i >= W_TOTAL) return;
    const float* W;
    int K, N, base;
    if      (i < WOFF_SO) { W = vp;  K = 256;  N = 256;  base = WOFF_VP; }
    else if (i < WOFF_AW) { W = so;  K = 256;  N = 256;  base = WOFF_SO; }
    else if (i < WOFF_OP) { W = awW; K = 256;  N = 128;  base = WOFF_AW; }
    else if (i < WOFF_L1) { W = op;  K = 256;  N = 256;  base = WOFF_OP; }
    else if (i < WOFF_L2) { W = l1;  K = 256;  N = 1024; base = WOFF_L1; }
    else                  { W = l2;  K = 1024; N = 256;  base = WOFF_L2; }
    const int li = i - base;
    const int n = li / K;
    const int k = li - n * K;
    const float v = W[(size_t)k * N + n];
    const __nv_bfloat16 hv = __float2bfloat16(v);
    h[i] = hv;
    l[i] = __float2bfloat16(v - __bfloat162float(hv));
}

// ---------------- deformable gather: 3-phase + high-MLP accumulation -------
// Block = one token m (8 warps = 8 heads).
// P0: 8 threads softmax the 16 logits of their head -> s_w
// P1: 128 threads compute 4 corner weights*w + PRE-SCALED indices (ci*D_)
// P2: 4 independent accumulators; samples in groups of 4 with all 16 LDG
//     issued before any FFMA (MLP ~16)
__global__ __launch_bounds__(256)
void gather_kernel(const float* __restrict__ value, const float* __restrict__ slocs,
                   const float* __restrict__ logits,
                   __nv_bfloat16* __restrict__ outh)
{
    __shared__ float s_w[128];
    __shared__ float s_cw[128 * 4];
    __shared__ int   s_ci[128 * 4];

    const int m = blockIdx.x;
    const int tid = threadIdx.x;
    const int b = m >> 12;

    if (tid < 8) {
        const float* lg = logits + (size_t)m * 128 + tid * 16;
        float w[16];
        float mx = -1e30f;
#pragma unroll
        for (int i = 0; i < 16; i++) { w[i] = lg[i]; mx = fmaxf(mx, w[i]); }
        float ssum = 0.f;
#pragma unroll
        for (int i = 0; i < 16; i++) { w[i] = __expf(w[i] - mx); ssum += w[i]; }
        const float sinv = 1.f / ssum;
#pragma unroll
        for (int i = 0; i < 16; i++) s_w[tid * 16 + i] = w[i] * sinv;
    }
    __syncthreads();

    if (tid < 128) {
        const int h = tid >> 4;
        const int s = tid & 15;
        const int l = s >> 2;
        const float* sl = slocs + (((size_t)m * NH + h) * 16 + s) * 2;
        const float x = sl[0] * (float)WS - 0.5f;
        const float y = sl[1] * (float)HS - 0.5f;
        const float ww = s_w[tid];
        const float x0f = floorf(x);
        const float y0f = floorf(y);
        const int x0 = (int)x0f;
        const int y0 = (int)y0f;
        const float lx = x - x0f;
        const float ly = y - y0f;
        const int vbase = b * LQ + l * HW;
#pragma unroll
        for (int dy = 0; dy < 2; dy++) {
            const int yi = y0 + dy;
            const float wy = dy ? ly : (1.f - ly);
#pragma unroll
            for (int dx = 0; dx < 2; dx++) {
                const int xi = x0 + dx;
                const float wx = dx ? lx : (1.f - lx);
                const bool valid = (yi >= 0) & (yi < HS) & (xi >= 0) & (xi < WS);
                const int yc = min(max(yi, 0), HS - 1);
                const int xc = min(max(xi, 0), WS - 1);
                const int ci = tid * 4 + dy * 2 + dx;
                s_cw[ci] = valid ? (ww * wy * wx) : 0.f;
                s_ci[ci] = (vbase + yc * WS + xc) * D_;   // pre-scaled by row stride
            }
        }
    }
    __syncthreads();

    const int h = tid >> 5;
    const int d = tid & 31;
    const int hb = h * HD + d;

    float acc0 = 0.f, acc1 = 0.f, acc2 = 0.f, acc3 = 0.f;
#pragma unroll
    for (int g = 0; g < 4; g++) {
        float4 cw[4];
        int4   ci[4];
#pragma unroll
        for (int s = 0; s < 4; s++) {
            const int si = (h * 16 + g * 4 + s) * 4;
            cw[s] = *(const float4*)&s_cw[si];
            ci[s] = *(const int4*)&s_ci[si];
        }
        float v[16];
#pragma unroll
        for (int s = 0; s < 4; s++) {
            v[s * 4 + 0] = value[ci[s].x + hb];
            v[s * 4 + 1] = value[ci[s].y + hb];
            v[s * 4 + 2] = value[ci[s].z + hb];
            v[s * 4 + 3] = value[ci[s].w + hb];
        }
#pragma unroll
        for (int s = 0; s < 4; s++) {
            acc0 = fmaf(cw[s].x, v[s * 4 + 0], acc0);
            acc1 = fmaf(cw[s].y, v[s * 4 + 1], acc1);
            acc2 = fmaf(cw[s].z, v[s * 4 + 2], acc2);
            acc3 = fmaf(cw[s].w, v[s * 4 + 3], acc3);
        }
    }
    const float acc = (acc0 + acc1) + (acc2 + acc3);
    outh[(size_t)m * D_ + hb] = __float2bfloat16(acc);
}

// ---------------- layernorm over 256 cols; one warp per row ----------------
// MODE 0: fp32 out only. MODE 1: fp32 out + bf16 out.
template<int MODE>
__global__ __launch_bounds__(256)
void layernorm_kernel(const float* __restrict__ in, const float* __restrict__ g,
                      const float* __restrict__ b, float* __restrict__ out,
                      __nv_bfloat16* __restrict__ outh)
{
    const int row = blockIdx.x * 8 + (threadIdx.x >> 5);
    const int lane = threadIdx.x & 31;
    const float* r = in + (size_t)row * D_;
    float v[8];
    float s = 0.f, s2 = 0.f;
#pragma unroll
    for (int i = 0; i < 8; i++) {
        v[i] = r[i * 32 + lane];
        s += v[i];
        s2 = fmaf(v[i], v[i], s2);
    }
#pragma unroll
    for (int o = 16; o > 0; o >>= 1) {
        s  += __shfl_xor_sync(0xffffffff, s, o);
        s2 += __shfl_xor_sync(0xffffffff, s2, o);
    }
    const float mean = s * (1.f / 256.f);
    const float var  = s2 * (1.f / 256.f) - mean * mean;
    const float inv  = rsqrtf(var + 1e-5f);
#pragma unroll
    for (int i = 0; i < 8; i++) {
        const int c = i * 32 + lane;
        const float u = (v[i] - mean) * inv * g[c] + b[c];
        out[(size_t)row * D_ + c] = u;
        if (MODE == 1) outh[(size_t)row * D_ + c] = __float2bfloat16(u);
    }
}

// ---------------- host launch ----------------
extern "C" void kernel_launch(void* const* d_in, const int* in_sizes, int n_in,
                              void* d_out, int out_size)
{
    const float* src    = (const float*)d_in[0];
    // d_in[1] = pos (unused by the reference forward)
    const float* refpts = (const float*)d_in[2];
    const float* vp_w   = (const float*)d_in[3];
    const float* vp_b   = (const float*)d_in[4];
    const float* so_w   = (const float*)d_in[5];
    const float* so_b   = (const float*)d_in[6];
    const float* aw_w   = (const float*)d_in[7];
    const float* aw_b   = (const float*)d_in[8];
    const float* op_w   = (const float*)d_in[9];
    const float* op_b   = (const float*)d_in[10];
    const float* n1_g   = (const float*)d_in[11];
    const float* n1_b   = (const float*)d_in[12];
    const float* l1_w   = (const float*)d_in[13];
    const float* l1_b   = (const float*)d_in[14];
    const float* l2_w   = (const float*)d_in[15];
    const float* l2_b   = (const float*)d_in[16];
    const float* n2_g   = (const float*)d_in[17];
    const float* n2_b   = (const float*)d_in[18];

    float* out_x = (float*)d_out;
    float* slocs = (float*)d_out + X_ELEMS;

    __nv_bfloat16 *src_h, *w_h, *w_l, *attn_h, *x1_h, *ffn_h;
    float *value, *aw, *tmpf, *x1;
    cudaGetSymbolAddress((void**)&src_h, g_src_h);
    cudaGetSymbolAddress((void**)&w_h,   g_w_h);
    cudaGetSymbolAddress((void**)&w_l,   g_w_l);
    cudaGetSymbolAddress((void**)&value, g_value);
    cudaGetSymbolAddress((void**)&aw,    g_aw);
    cudaGetSymbolAddress((void**)&attn_h, g_attn_h);
    cudaGetSymbolAddress((void**)&tmpf,  g_tmpf);
    cudaGetSymbolAddress((void**)&x1,    g_x1);
    cudaGetSymbolAddress((void**)&x1_h,  g_x1_h);
    cudaGetSymbolAddress((void**)&ffn_h, g_ffn_h);

    cudaFuncSetAttribute(mma_gemm<2>, cudaFuncAttributeMaxDynamicSharedMemorySize, SMEM_TOT);
    cudaFuncSetAttribute(mma_gemm<3>, cudaFuncAttributeMaxDynamicSharedMemorySize, SMEM_TOT);
    cudaFuncSetAttribute(mma_gemm<4>, cudaFuncAttributeMaxDynamicSharedMemorySize, SMEM_TOT);

    // 0) conversions (2 launches)
    conv_h_kernel<<<(M_TOK * D_ + 255) / 256, 256>>>(src, src_h, M_TOK * D_);
    prep_all_kernel<<<(W_TOTAL + 255) / 256, 256>>>(vp_w, so_w, aw_w, op_w, l1_w, l2_w, w_h, w_l);

    const dim3 blk(256);
    const dim3 gfused(640 / 64, M_TOK / 128);  // (10, 64) = 640 CTAs
    const dim3 g256(256 / 64, M_TOK / 128);    // (4, 64)
    const dim3 g1024(1024 / 64, M_TOK / 128);  // (16, 64)

    // 1) fused: value | sampling_locations | attn logits
    mma_gemm<4><<<gfused, blk, SMEM_TOT>>>(src_h, w_h, w_l,
                                           vp_b, so_b, aw_b, nullptr, refpts,
                                           value, slocs, aw, nullptr, 640, 256);
    // 2) gather (softmax fused) -> attn bf16
    gather_kernel<<<M_TOK, 256>>>(value, slocs, aw, attn_h);
    // 3) out_proj + residual(src) -> tmpf
    mma_gemm<3><<<g256, blk, SMEM_TOT>>>(attn_h, w_h + WOFF_OP, w_l + WOFF_OP,
                                         op_b, nullptr, nullptr, src, nullptr,
                                         tmpf, nullptr, nullptr, nullptr, 256, 256);
    // 4) LN1 -> x1 (fp32 + bf16)
    layernorm_kernel<1><<<M_TOK / 8, 256>>>(tmpf, n1_g, n1_b, x1, x1_h);
    // 5) FFN1: relu -> ffn bf16
    mma_gemm<2><<<g1024, blk, SMEM_TOT>>>(x1_h, w_h + WOFF_L1, w_l + WOFF_L1,
                                          l1_b, nullptr, nullptr, nullptr, nullptr,
                                          nullptr, nullptr, nullptr, ffn_h, 1024, 256);
    // 6) FFN2 + residual(x1) -> tmpf
    mma_gemm<3><<<g256, blk, SMEM_TOT>>>(ffn_h, w_h + WOFF_L2, w_l + WOFF_L2,
                                         l2_b, nullptr, nullptr, x1, nullptr,
                                         tmpf, nullptr, nullptr, nullptr, 256, 1024);
    // 7) LN2 -> final output
    layernorm_kernel<0><<<M_TOK / 8, 256>>>(tmpf, n2_g, n2_b, out_x, nullptr);
}